// round 16
// baseline (speedup 1.0000x reference)
#include <cuda_runtime.h>
#include <cstdint>

namespace {

constexpr int Bn = 256, Dn = 256, Nn = 1024;
constexpr int TPB = 512, GRID = 256;          // one batch per CTA, 2 CTAs/SM
constexpr int TS = 32, NT = Nn / TS;          // 32 tiles of 32 columns
constexpr float EPS_NORM = 1e-12f;
constexpr float EPS_DIV  = 1e-5f;

// Block-wide sum over 512 threads (16 warps). All threads must call.
__device__ __forceinline__ float block_reduce(float val, float* red) {
#pragma unroll
    for (int o = 16; o; o >>= 1) val += __shfl_down_sync(0xffffffffu, val, o);
    const int lane = threadIdx.x & 31;
    const int w    = threadIdx.x >> 5;
    if (lane == 0) red[w] = val;
    __syncthreads();
    if (w == 0) {
        val = (lane < 16) ? red[lane] : 0.f;
#pragma unroll
        for (int o = 8; o; o >>= 1) val += __shfl_down_sync(0xffffffffu, val, o);
        if (lane == 0) red[0] = val;
    }
    __syncthreads();
    float r = red[0];
    __syncthreads();
    return r;
}

// Two simultaneous block-wide sums (one barrier trip for both).
__device__ __forceinline__ float2 block_reduce2(float a, float b, float* red) {
#pragma unroll
    for (int o = 16; o; o >>= 1) {
        a += __shfl_down_sync(0xffffffffu, a, o);
        b += __shfl_down_sync(0xffffffffu, b, o);
    }
    const int lane = threadIdx.x & 31;
    const int w    = threadIdx.x >> 5;
    if (lane == 0) { red[w] = a; red[32 + w] = b; }
    __syncthreads();
    if (w == 0) {
        a = (lane < 16) ? red[lane] : 0.f;
        b = (lane < 16) ? red[32 + lane] : 0.f;
#pragma unroll
        for (int o = 8; o; o >>= 1) {
            a += __shfl_down_sync(0xffffffffu, a, o);
            b += __shfl_down_sync(0xffffffffu, b, o);
        }
        if (lane == 0) { red[0] = a; red[32] = b; }
    }
    __syncthreads();
    float2 r = make_float2(red[0], red[32]);
    __syncthreads();
    return r;
}

__global__ __launch_bounds__(TPB, 2) void svpn_kernel(
    const float* __restrict__ x,       // (B, D, N)
    const float* __restrict__ weight,  // (D,)
    float* __restrict__ out)           // (B, D*N)
{
    __shared__ float wpart[64 * TS];   // 64 row-groups x 32 cols
    __shared__ float zsc[Dn * 9];      // 256 rows x 8 quads (pad 9)
    __shared__ float ucur[Nn];         // unnormalized w (ends as u2)
    __shared__ float u1[Nn];           // normalized u of component 1
    __shared__ float vv[Dn];
    __shared__ float v1[Dn];
    __shared__ float ws[TS];
    __shared__ float red[64];
    __shared__ float sS[2];

    const int tid = threadIdx.x;
    const int q4   = tid & 7;          // column quad: cols 4*q4..4*q4+3 in tile
    const int rowg = tid >> 3;         // row group: rows 4*rowg..4*rowg+3

    const int b = blockIdx.x;
    const float* xb = x + (size_t)b * (Dn * Nn);
    const float4* xb4 = reinterpret_cast<const float4*>(xb);

    if (tid < Dn) vv[tid] = weight[tid];
    __syncthreads();

    float s1 = 0.f, c_u = 0.f;

    for (int sv = 0; sv < 2; ++sv) {
        for (int it = 0; it < 3; ++it) {
            float zpart[4];
#pragma unroll
            for (int i = 0; i < 4; ++i) zpart[i] = 0.f;

            float4 xA[4], xB[4];
            // load tile 0 strip
#pragma unroll
            for (int i = 0; i < 4; ++i)
                xA[i] = xb4[(size_t)(rowg * 4 + i) * (Nn / 4) + q4];

            auto tile_body = [&](int t, float4 (&cur)[4], float4 (&nxt)[4]) {
                if (t + 1 < NT) {
#pragma unroll
                    for (int i = 0; i < 4; ++i)
                        nxt[i] = xb4[(size_t)(rowg * 4 + i) * (Nn / 4)
                                     + (t + 1) * (TS / 4) + q4];
                }
                // w-phase: per-column partials over this thread's 4 rows
                float4 wp = make_float4(0.f, 0.f, 0.f, 0.f);
#pragma unroll
                for (int i = 0; i < 4; ++i) {
                    const float vvi = vv[rowg * 4 + i];
                    wp.x = fmaf(cur[i].x, vvi, wp.x);
                    wp.y = fmaf(cur[i].y, vvi, wp.y);
                    wp.z = fmaf(cur[i].z, vvi, wp.z);
                    wp.w = fmaf(cur[i].w, vvi, wp.w);
                }
                *reinterpret_cast<float4*>(&wpart[rowg * TS + q4 * 4]) = wp;
                __syncthreads();

                // reduce 64 row-groups -> ws (32 cols) + u-side deflation
                if (tid < TS) {
                    float a0 = 0.f, a1 = 0.f, a2 = 0.f, a3 = 0.f;
#pragma unroll
                    for (int gg = 0; gg < 64; gg += 4) {
                        a0 += wpart[(gg + 0) * TS + tid];
                        a1 += wpart[(gg + 1) * TS + tid];
                        a2 += wpart[(gg + 2) * TS + tid];
                        a3 += wpart[(gg + 3) * TS + tid];
                    }
                    float wsum = (a0 + a1) + (a2 + a3);
                    if (sv) wsum -= c_u * u1[t * TS + tid];
                    ws[tid] = wsum;
                    ucur[t * TS + tid] = wsum;
                }
                __syncthreads();

                // z-phase: accumulate row dots in registers
                const float4 wv4 = *reinterpret_cast<const float4*>(&ws[q4 * 4]);
#pragma unroll
                for (int i = 0; i < 4; ++i)
                    zpart[i] = fmaf(cur[i].x, wv4.x,
                               fmaf(cur[i].y, wv4.y,
                               fmaf(cur[i].z, wv4.z,
                               fmaf(cur[i].w, wv4.w, zpart[i]))));
            };

            for (int tt = 0; tt < NT / 2; ++tt) {
                tile_body(2 * tt,     xA, xB);
                tile_body(2 * tt + 1, xB, xA);
            }

            // dump z partials: row = rowg*4+i, quad q4
#pragma unroll
            for (int i = 0; i < 4; ++i)
                zsc[(rowg * 4 + i) * 9 + q4] = zpart[i];

            // scalar partials ||w||^2, u1.w (2 elems/thread; barrier inside
            // also publishes zsc)
            float wa = ucur[tid], wb = ucur[tid + 512];
            float u1w = sv ? (u1[tid] * wa + u1[tid + 512] * wb) : 0.f;
            float2 sc = block_reduce2(wa * wa + wb * wb, u1w, red);

            float zd = 0.f;
            if (tid < Dn) {
                float a0 = 0.f, a1 = 0.f;
#pragma unroll
                for (int q = 0; q < 8; q += 2) {
                    a0 += zsc[tid * 9 + q];
                    a1 += zsc[tid * 9 + q + 1];
                }
                zd = a0 + a1;
                if (sv) zd -= s1 * sc.y * v1[tid];     // z-side deflation
            }
            float2 zr = block_reduce2((tid < Dn) ? zd * zd : 0.f,
                                      (tid < Dn) ? v1[tid] * zd : 0.f, red);
            const float nz  = sqrtf(zr.x);
            const float nzc = fmaxf(nz, EPS_NORM);
            if (tid < Dn) vv[tid] = zd / nzc;
            c_u = s1 * (zr.y / nzc);                   // s1*(v1 . v_new)

            if (it == 2) {
                const float nw_  = fmaxf(sqrtf(sc.x), EPS_NORM);
                const float invw = 1.f / nw_;
                const float sval = nz / nw_;           // s = ||A^T u||
                if (sv == 0) {
                    u1[tid]       = ucur[tid] * invw;
                    u1[tid + 512] = ucur[tid + 512] * invw;
                    if (tid < Dn) v1[tid] = zd / nzc;
                    if (tid == 0) sS[0] = sval;
                } else {
                    ucur[tid]       *= invw;           // ucur becomes u2
                    ucur[tid + 512] *= invw;
                    if (tid == 0) sS[1] = sval;
                }
            }
            __syncthreads();
        }  // it

        if (sv == 0) {
            s1 = sS[0];
            if (tid < Dn) vv[tid] = weight[tid];
            __syncthreads();
            float pr = (tid < Dn) ? v1[tid] * vv[tid] : 0.f;
            c_u = s1 * block_reduce(pr, red);
        }
    }  // sv

    // epilogue: out = c*x + c1*u1 v1^T + c2*u2 v2^T
    const float s1f = sS[0], s2f = sS[1];
    const float c  = 1.f / (sqrtf(s2f) + EPS_DIV);
    const float c1 = sqrtf(s1f) - s1f * c;
    const float c2 = sqrtf(s2f) - s2f * c;

    float4*       o4  = reinterpret_cast<float4*>(out + (size_t)b * (Dn * Nn));
    const float4* u14 = reinterpret_cast<const float4*>(u1);
    const float4* u24 = reinterpret_cast<const float4*>(ucur);  // u2

    constexpr int TOT4 = Dn * Nn / 4;  // 65536
#pragma unroll 4
    for (int idx = tid; idx < TOT4; idx += TPB) {
        const int d   = idx >> 8;
        const int col = idx & 255;
        const float a1 = c1 * v1[d];
        const float a2 = c2 * vv[d];   // vv holds v2
        const float4 xv = __ldcs(&xb4[idx]);
        const float4 uA = u14[col];
        const float4 uB = u24[col];
        float4 o;
        o.x = fmaf(c, xv.x, fmaf(a1, uA.x, a2 * uB.x));
        o.y = fmaf(c, xv.y, fmaf(a1, uA.y, a2 * uB.y));
        o.z = fmaf(c, xv.z, fmaf(a1, uA.z, a2 * uB.z));
        o.w = fmaf(c, xv.w, fmaf(a1, uA.w, a2 * uB.w));
        __stcs(&o4[idx], o);
    }
}

}  // namespace

extern "C" void kernel_launch(void* const* d_in, const int* in_sizes, int n_in,
                              void* d_out, int out_size) {
    const float* x = (const float*)d_in[0];
    const float* w = (const float*)d_in[1];
    if (n_in >= 2 && in_sizes[0] < in_sizes[1]) {
        const float* t = x; x = w; w = t;
    }
    svpn_kernel<<<GRID, TPB>>>(x, w, (float*)d_out);
}

// round 17
// speedup vs baseline: 1.2973x; 1.2973x over previous
#include <cuda_runtime.h>
#include <cstdint>

namespace {

constexpr int Bn = 256, Dn = 256, Nn = 1024;
constexpr int TPB = 1024, GRID = 128;
constexpr int TS = 64, NT = Nn / TS;          // 16 tiles of 64 columns
constexpr float EPS_NORM = 1e-12f;
constexpr float EPS_DIV  = 1e-5f;

// dynamic smem layout (float offsets)
constexpr int OFF_SBUF  = 0;                  // 2 bufs x 1024 thr x 4 float4 = 32768
constexpr int OFF_WPART = 32768;              // 2 x (64 groups x 64 cols) = 8192
constexpr int OFF_ZSC   = OFF_WPART + 8192;   // 256 x 17 = 4352
constexpr int OFF_UCUR  = OFF_ZSC + 4352;     // 1024
constexpr int OFF_U1    = OFF_UCUR + 1024;    // 1024
constexpr int OFF_VV    = OFF_U1 + 1024;      // 256
constexpr int OFF_V1    = OFF_VV + 256;       // 256
constexpr int OFF_WS    = OFF_V1 + 256;       // 2 x 64
constexpr int OFF_RED   = OFF_WS + 128;       // 64
constexpr int OFF_SS    = OFF_RED + 64;       // 2
constexpr int SMEM_BYTES = (OFF_SS + 4) * 4;  // ~188 KB

__device__ __forceinline__ void cp16(void* dst_smem, const void* src) {
    unsigned d = (unsigned)__cvta_generic_to_shared(dst_smem);
    asm volatile("cp.async.cg.shared.global [%0], [%1], 16;" :: "r"(d), "l"(src));
}
__device__ __forceinline__ void cp_commit() {
    asm volatile("cp.async.commit_group;" ::: "memory");
}
__device__ __forceinline__ void cp_wait1() {
    asm volatile("cp.async.wait_group 1;" ::: "memory");
}

// Block-wide sum over 1024 threads (32 warps). All threads must call.
__device__ __forceinline__ float block_reduce(float val, float* red) {
#pragma unroll
    for (int o = 16; o; o >>= 1) val += __shfl_down_sync(0xffffffffu, val, o);
    const int lane = threadIdx.x & 31;
    const int w    = threadIdx.x >> 5;
    if (lane == 0) red[w] = val;
    __syncthreads();
    if (w == 0) {
        val = red[lane];
#pragma unroll
        for (int o = 16; o; o >>= 1) val += __shfl_down_sync(0xffffffffu, val, o);
        if (lane == 0) red[0] = val;
    }
    __syncthreads();
    float r = red[0];
    __syncthreads();
    return r;
}

// Two simultaneous block-wide sums (one barrier trip for both).
__device__ __forceinline__ float2 block_reduce2(float a, float b, float* red) {
#pragma unroll
    for (int o = 16; o; o >>= 1) {
        a += __shfl_down_sync(0xffffffffu, a, o);
        b += __shfl_down_sync(0xffffffffu, b, o);
    }
    const int lane = threadIdx.x & 31;
    const int w    = threadIdx.x >> 5;
    if (lane == 0) { red[w] = a; red[32 + w] = b; }
    __syncthreads();
    if (w == 0) {
        a = red[lane];
        b = red[32 + lane];
#pragma unroll
        for (int o = 16; o; o >>= 1) {
            a += __shfl_down_sync(0xffffffffu, a, o);
            b += __shfl_down_sync(0xffffffffu, b, o);
        }
        if (lane == 0) { red[0] = a; red[32] = b; }
    }
    __syncthreads();
    float2 r = make_float2(red[0], red[32]);
    __syncthreads();
    return r;
}

__global__ __launch_bounds__(TPB, 1) void svpn_kernel(
    const float* __restrict__ x,       // (B, D, N)
    const float* __restrict__ weight,  // (D,)
    float* __restrict__ out)           // (B, D*N)
{
    extern __shared__ float sm[];
    float4* sbuf4 = reinterpret_cast<float4*>(sm + OFF_SBUF);
    float*  wpart = sm + OFF_WPART;   // [2][64*64]
    float*  zsc   = sm + OFF_ZSC;
    float*  ucur  = sm + OFF_UCUR;    // unnormalized w (ends as u2)
    float*  u1    = sm + OFF_U1;      // normalized u of component 1
    float*  vv    = sm + OFF_VV;
    float*  v1    = sm + OFF_V1;
    float*  ws    = sm + OFF_WS;      // [2][64]
    float*  red   = sm + OFF_RED;
    float*  sS    = sm + OFF_SS;

    const int tid   = threadIdx.x;
    const int lane  = tid & 31;
    const int w     = tid >> 5;
    const int q4    = tid & 15;        // column quad within 64-col tile
    const int g     = tid >> 4;        // row group 0..63
    const int g4row = g * 4;           // rows g4row..g4row+3

    // thread's private float4 slots in staging buffer b: index (b*32+w)*128 + i*32 + lane
    const int sslot = w * 128 + lane;

    for (int b = blockIdx.x; b < Bn; b += GRID) {
        const float* xb = x + (size_t)b * (Dn * Nn);
        const float4* xb4 = reinterpret_cast<const float4*>(xb);
        if (tid < Dn) vv[tid] = weight[tid];
        __syncthreads();

        float s1 = 0.f, c_u = 0.f;

        for (int sv = 0; sv < 2; ++sv) {
            for (int it = 0; it < 3; ++it) {
                float vreg[4];
#pragma unroll
                for (int i = 0; i < 4; ++i) vreg[i] = vv[g4row + i];

                float zpart[4] = {0.f, 0.f, 0.f, 0.f};
                float4 sA[4], sB[4];

                // prologue: queue tiles 0 and 1 (private strips)
#pragma unroll
                for (int i = 0; i < 4; ++i)
                    cp16(&sbuf4[sslot + i * 32],
                         &xb4[(size_t)(g4row + i) * 256 + q4]);
                cp_commit();
#pragma unroll
                for (int i = 0; i < 4; ++i)
                    cp16(&sbuf4[4096 + sslot + i * 32],
                         &xb4[(size_t)(g4row + i) * 256 + 16 + q4]);
                cp_commit();

                // region1: wait tile t, LDS strip, w-partials, prefetch t+2
                auto region1 = [&](int t, float4 (&cur)[4]) {
                    cp_wait1();
                    const int base = (t & 1) * 4096 + sslot;
#pragma unroll
                    for (int i = 0; i < 4; ++i) cur[i] = sbuf4[base + i * 32];
                    float4 wp = make_float4(0.f, 0.f, 0.f, 0.f);
#pragma unroll
                    for (int i = 0; i < 4; ++i) {
                        wp.x = fmaf(cur[i].x, vreg[i], wp.x);
                        wp.y = fmaf(cur[i].y, vreg[i], wp.y);
                        wp.z = fmaf(cur[i].z, vreg[i], wp.z);
                        wp.w = fmaf(cur[i].w, vreg[i], wp.w);
                    }
                    *reinterpret_cast<float4*>(
                        &wpart[(t & 1) * 4096 + (tid << 2)]) = wp;
                    if (t + 2 < NT) {
#pragma unroll
                        for (int i = 0; i < 4; ++i)
                            cp16(&sbuf4[(t & 1) * 4096 + sslot + i * 32],
                                 &xb4[(size_t)(g4row + i) * 256
                                      + (t + 2) * 16 + q4]);
                    }
                    cp_commit();
                };

                // z accumulate for tile tp using prev regs and ws[tp&1]
                auto zphase = [&](int tp, float4 (&prev)[4]) {
                    const float4 wv4 = *reinterpret_cast<const float4*>(
                        &ws[(tp & 1) * 64 + (q4 << 2)]);
#pragma unroll
                    for (int i = 0; i < 4; ++i)
                        zpart[i] = fmaf(prev[i].x, wv4.x,
                                   fmaf(prev[i].y, wv4.y,
                                   fmaf(prev[i].z, wv4.z,
                                   fmaf(prev[i].w, wv4.w, zpart[i]))));
                };

                // ws reduce for tile t (2 warps)
                auto wreduce = [&](int t) {
                    if (tid < TS) {
                        const float* wpb = &wpart[(t & 1) * 4096];
                        float a0 = 0.f, a1 = 0.f, a2 = 0.f, a3 = 0.f;
#pragma unroll
                        for (int gg = 0; gg < 64; gg += 4) {
                            a0 += wpb[(gg + 0) * 64 + tid];
                            a1 += wpb[(gg + 1) * 64 + tid];
                            a2 += wpb[(gg + 2) * 64 + tid];
                            a3 += wpb[(gg + 3) * 64 + tid];
                        }
                        float wsum = (a0 + a1) + (a2 + a3);
                        if (sv) wsum -= c_u * u1[t * TS + tid];
                        ws[(t & 1) * 64 + tid] = wsum;
                        ucur[t * TS + tid] = wsum;
                    }
                };

                for (int t = 0; t < NT; t += 2) {
                    region1(t, sA);
                    __syncthreads();
                    if (t > 0) zphase(t - 1, sB);
                    wreduce(t);

                    region1(t + 1, sB);
                    __syncthreads();
                    zphase(t, sA);
                    wreduce(t + 1);
                }
                __syncthreads();            // ws[NT-1] published
                zphase(NT - 1, sB);

                // dump z partials: row = g4row+i, quad q4 (pad 17)
#pragma unroll
                for (int i = 0; i < 4; ++i)
                    zsc[(g4row + i) * 17 + q4] = zpart[i];

                // scalar partials ||w||^2, u1.w (barrier inside publishes zsc)
                float wv_ = ucur[tid];
                float2 sc = block_reduce2(wv_ * wv_,
                                          sv ? u1[tid] * wv_ : 0.f, red);

                float zd = 0.f;
                if (tid < Dn) {
                    float a0 = 0.f, a1 = 0.f;
#pragma unroll
                    for (int q = 0; q < 16; q += 2) {
                        a0 += zsc[tid * 17 + q];
                        a1 += zsc[tid * 17 + q + 1];
                    }
                    zd = a0 + a1;
                    if (sv) zd -= s1 * sc.y * v1[tid];   // z-side deflation
                }
                float2 zr = block_reduce2((tid < Dn) ? zd * zd : 0.f,
                                          (tid < Dn) ? v1[tid] * zd : 0.f, red);
                const float nz  = sqrtf(zr.x);
                const float nzc = fmaxf(nz, EPS_NORM);
                if (tid < Dn) vv[tid] = zd / nzc;
                c_u = s1 * (zr.y / nzc);                 // s1*(v1 . v_new)

                if (it == 2) {
                    const float nw_  = fmaxf(sqrtf(sc.x), EPS_NORM);
                    const float invw = 1.f / nw_;
                    const float sval = nz / nw_;         // s = ||A^T u||
                    if (sv == 0) {
                        u1[tid] = ucur[tid] * invw;
                        if (tid < Dn) v1[tid] = zd / nzc;
                        if (tid == 0) sS[0] = sval;
                    } else {
                        ucur[tid] *= invw;               // ucur becomes u2
                        if (tid == 0) sS[1] = sval;
                    }
                }
                __syncthreads();
            }  // it

            if (sv == 0) {
                s1 = sS[0];
                if (tid < Dn) vv[tid] = weight[tid];
                __syncthreads();
                float pr = (tid < Dn) ? v1[tid] * vv[tid] : 0.f;
                c_u = s1 * block_reduce(pr, red);
            }
        }  // sv

        // epilogue: out = c*x + c1*u1 v1^T + c2*u2 v2^T
        const float s1f = sS[0], s2f = sS[1];
        const float c  = 1.f / (sqrtf(s2f) + EPS_DIV);
        const float c1 = sqrtf(s1f) - s1f * c;
        const float c2 = sqrtf(s2f) - s2f * c;

        float4*       o4  = reinterpret_cast<float4*>(out + (size_t)b * (Dn * Nn));
        const float4* u14 = reinterpret_cast<const float4*>(u1);
        const float4* u24 = reinterpret_cast<const float4*>(ucur);  // u2

        constexpr int TOT4 = Dn * Nn / 4;  // 65536
#pragma unroll 8
        for (int idx = tid; idx < TOT4; idx += TPB) {
            const int d   = idx >> 8;
            const int col = idx & 255;
            const float a1 = c1 * v1[d];
            const float a2 = c2 * vv[d];   // vv holds v2
            const float4 xv = __ldcs(&xb4[idx]);
            const float4 uA = u14[col];
            const float4 uB = u24[col];
            float4 o;
            o.x = fmaf(c, xv.x, fmaf(a1, uA.x, a2 * uB.x));
            o.y = fmaf(c, xv.y, fmaf(a1, uA.y, a2 * uB.y));
            o.z = fmaf(c, xv.z, fmaf(a1, uA.z, a2 * uB.z));
            o.w = fmaf(c, xv.w, fmaf(a1, uA.w, a2 * uB.w));
            __stcs(&o4[idx], o);
        }
        __syncthreads();  // protect smem before next batch
    }  // batch loop
}

}  // namespace

extern "C" void kernel_launch(void* const* d_in, const int* in_sizes, int n_in,
                              void* d_out, int out_size) {
    const float* x = (const float*)d_in[0];
    const float* w = (const float*)d_in[1];
    if (n_in >= 2 && in_sizes[0] < in_sizes[1]) {
        const float* t = x; x = w; w = t;
    }
    cudaFuncSetAttribute(svpn_kernel, cudaFuncAttributeMaxDynamicSharedMemorySize,
                         SMEM_BYTES);
    svpn_kernel<<<GRID, TPB, SMEM_BYTES>>>(x, w, (float*)d_out);
}